// round 2
// baseline (speedup 1.0000x reference)
#include <cuda_runtime.h>
#include <cuda_bf16.h>

typedef unsigned long long ull;

// ---------------- constants ----------------
#define BB     16
#define LL     4096
#define DD     512
#define H1     256
#define DE     64
#define PATCH  16
#define STRIDE 8
#define HP     511            // patches per batch
#define NP     (BB*HP)        // 8176 patch rows
#define NR     (BB*LL)        // 65536 token rows
#define EPSF   1e-8f

// ---------------- scratch (device globals; no allocation) ----------------
__device__ float g_Xe[(size_t)NR * DE];   // encoded tokens (16.8 MB)
__device__ float g_z [(size_t)NP * DE];   // per-patch aggregated z (2.1 MB)

// ---------------- f32x2 helpers ----------------
__device__ __forceinline__ ull ffma2(ull a, ull b, ull c) {
    ull d;
    asm("fma.rn.f32x2 %0, %1, %2, %3;" : "=l"(d) : "l"(a), "l"(b), "l"(c));
    return d;
}
__device__ __forceinline__ ull pack2(float lo, float hi) {
    ull r;
    asm("mov.b64 %0, {%1, %2};" : "=l"(r) : "f"(lo), "f"(hi));
    return r;
}
__device__ __forceinline__ float2 unpack2(ull v) {
    float2 f;
    asm("mov.b64 {%0, %1}, %2;" : "=f"(f.x), "=f"(f.y) : "l"(v));
    return f;
}
__device__ __forceinline__ float leaky(float x) { return x > 0.f ? x : 0.01f * x; }

// ============================================================
// Kernel 1: fused encoder.  64 rows/block, 256 threads.
// stage1: H = leaky(X @ W1 + b1)   (64 x 256, K=512)
// stage2: Xe = H @ W2 + b2         (64 x 64,  K=256)
// ============================================================
#define ENC_SMEM (9216 + 16384 + 66560 + 4096)   // Xs2 | Ws1 | Hs | W2s = 96256 B

__global__ void __launch_bounds__(256, 2)
enc_kernel(const float* __restrict__ X,
           const float* __restrict__ We1, const float* __restrict__ be1,
           const float* __restrict__ We2, const float* __restrict__ be2)
{
    extern __shared__ unsigned char sm[];
    ull   (*Xs2)[18]  = reinterpret_cast<ull(*)[18]>(sm);            // dup-packed X tile [64][16]
    float (*Ws1)[256] = reinterpret_cast<float(*)[256]>(sm + 9216);  // W1 tile [16][256]
    float (*Hs)[260]  = reinterpret_cast<float(*)[260]>(sm + 25600); // hidden [64][256] padded
    float (*W2s)[64]  = reinterpret_cast<float(*)[64]>(sm + 92160);  // W2 tile [16][64]

    const int tid  = threadIdx.x;
    const int w    = tid >> 5;
    const int lane = tid & 31;
    const int r0   = blockIdx.x * 64;
    const int rb   = w * 8;        // 8 warps x 8 rows
    const int cb   = lane * 8;     // 32 lanes x 8 cols = 256

    ull acc[8][4];
    #pragma unroll
    for (int r = 0; r < 8; ++r)
        #pragma unroll
        for (int p = 0; p < 4; ++p) acc[r][p] = 0ull;

    for (int kt = 0; kt < DD; kt += 16) {
        // load X tile (64 rows x 16 k), duplicated into u64 pairs
        {
            int row = tid >> 2, q = tid & 3;
            float4 g = *(const float4*)(X + (size_t)(r0 + row) * DD + kt + q * 4);
            Xs2[row][q * 4 + 0] = pack2(g.x, g.x);
            Xs2[row][q * 4 + 1] = pack2(g.y, g.y);
            Xs2[row][q * 4 + 2] = pack2(g.z, g.z);
            Xs2[row][q * 4 + 3] = pack2(g.w, g.w);
        }
        // load W1 tile (16 x 256)
        {
            const float4* src = (const float4*)(We1 + (size_t)kt * H1);
            float4* dst = (float4*)Ws1;
            #pragma unroll
            for (int i = 0; i < 4; ++i) dst[tid + i * 256] = src[tid + i * 256];
        }
        __syncthreads();

        #pragma unroll
        for (int k = 0; k < 16; k += 2) {
            ulonglong2 bA0 = *(const ulonglong2*)&Ws1[k][cb];
            ulonglong2 bA1 = *(const ulonglong2*)&Ws1[k][cb + 4];
            ulonglong2 bB0 = *(const ulonglong2*)&Ws1[k + 1][cb];
            ulonglong2 bB1 = *(const ulonglong2*)&Ws1[k + 1][cb + 4];
            #pragma unroll
            for (int r = 0; r < 8; ++r) {
                ulonglong2 a = *(const ulonglong2*)&Xs2[rb + r][k];
                acc[r][0] = ffma2(a.x, bA0.x, acc[r][0]);
                acc[r][1] = ffma2(a.x, bA0.y, acc[r][1]);
                acc[r][2] = ffma2(a.x, bA1.x, acc[r][2]);
                acc[r][3] = ffma2(a.x, bA1.y, acc[r][3]);
                acc[r][0] = ffma2(a.y, bB0.x, acc[r][0]);
                acc[r][1] = ffma2(a.y, bB0.y, acc[r][1]);
                acc[r][2] = ffma2(a.y, bB1.x, acc[r][2]);
                acc[r][3] = ffma2(a.y, bB1.y, acc[r][3]);
            }
        }
        __syncthreads();
    }

    // epilogue stage1: bias + leaky -> Hs
    #pragma unroll
    for (int p = 0; p < 4; ++p) {
        int c = cb + p * 2;
        float bx = be1[c], by = be1[c + 1];
        #pragma unroll
        for (int r = 0; r < 8; ++r) {
            float2 v = unpack2(acc[r][p]);
            float x0 = leaky(v.x + bx);
            float x1 = leaky(v.y + by);
            *(float2*)&Hs[rb + r][c] = make_float2(x0, x1);
        }
    }

    // stage2: Xe = Hs @ W2 + b2   (each warp: its 8 rows x all 64 cols, 2 cols/lane)
    const int c2 = lane * 2;
    ull acc2[8];
    {
        float b0 = be2[c2], b1f = be2[c2 + 1];
        #pragma unroll
        for (int r = 0; r < 8; ++r) acc2[r] = pack2(b0, b1f);
    }
    for (int kt = 0; kt < H1; kt += 16) {
        ((float4*)W2s)[tid] = ((const float4*)(We2 + (size_t)kt * DE))[tid];
        __syncthreads();
        #pragma unroll
        for (int k = 0; k < 16; k += 2) {
            ull w0 = *(const ull*)&W2s[k][c2];
            ull w1 = *(const ull*)&W2s[k + 1][c2];
            #pragma unroll
            for (int r = 0; r < 8; ++r) {
                float2 a = *(const float2*)&Hs[rb + r][kt + k];
                acc2[r] = ffma2(pack2(a.x, a.x), w0, acc2[r]);
                acc2[r] = ffma2(pack2(a.y, a.y), w1, acc2[r]);
            }
        }
        __syncthreads();
    }
    #pragma unroll
    for (int r = 0; r < 8; ++r)
        *(ull*)&g_Xe[(size_t)(r0 + rb + r) * DE + c2] = acc2[r];
}

// ============================================================
// Kernel 2: patch attention.  One block (128 thr) per patch row.
// ============================================================
__global__ void __launch_bounds__(128)
attn_kernel(const float* __restrict__ Wq, const float* __restrict__ Wk,
            const float* __restrict__ Wv, const float* __restrict__ Wagg,
            const float* __restrict__ bagg)
{
    __shared__ float pp[64], sq[64], sk[64], sv[64], av[64], tmp[128];
    __shared__ float sinvq, sinvk;

    const int n = blockIdx.x;
    const int b = n / HP;
    const int p = n % HP;
    const int tid = threadIdx.x;

    // patch mean over 16 tokens
    {
        int d = tid & 63, half = tid >> 6;
        const float* base = g_Xe + ((size_t)b * LL + p * STRIDE + half * 8) * DE + d;
        float s = 0.f;
        #pragma unroll
        for (int t = 0; t < 8; ++t) s += base[t * DE];
        tmp[tid] = s;
    }
    __syncthreads();
    if (tid < 64) pp[tid] = (tmp[tid] + tmp[tid + 64]) * 0.0625f;
    __syncthreads();

    // q, k, v
    if (tid < 64) {
        float aq = 0.f, ak = 0.f, avv = 0.f;
        #pragma unroll 8
        for (int e = 0; e < 64; ++e) {
            float x = pp[e];
            aq  = fmaf(x, Wq[e * 64 + tid], aq);
            ak  = fmaf(x, Wk[e * 64 + tid], ak);
            avv = fmaf(x, Wv[e * 64 + tid], avv);
        }
        sq[tid] = aq; sk[tid] = ak; sv[tid] = avv;
    }
    __syncthreads();

    // norms
    if (tid < 64) {
        int lane = tid & 31;
        bool isQ = tid < 32;
        const float* arr = isQ ? sq : sk;
        float s2 = arr[lane] * arr[lane] + arr[lane + 32] * arr[lane + 32];
        #pragma unroll
        for (int off = 16; off; off >>= 1) s2 += __shfl_xor_sync(0xffffffffu, s2, off);
        float inv = 1.0f / (sqrtf(s2) + EPSF);
        if (lane == 0) { if (isQ) sinvq = inv; else sinvk = inv; }
    }
    __syncthreads();
    if (tid < 64) { sq[tid] *= sinvq; sk[tid] *= sinvk; }
    __syncthreads();

    // attention rows: warp w handles rows w*16 .. w*16+15, each lane owns cols (lane, lane+32)
    const int w = tid >> 5, lane = tid & 31;
    const float knj0 = sk[lane], knj1 = sk[lane + 32];
    const float qnj0 = sq[lane], qnj1 = sq[lane + 32];
    const float vj0  = sv[lane], vj1  = sv[lane + 32];

    for (int ii = 0; ii < 16; ++ii) {
        int i = w * 16 + ii;
        float qi = sq[i], ki = sk[i];
        float a0 = fmaxf(tanhf(qi * knj0 - ki * qnj0), 0.f);
        float a1 = fmaxf(tanhf(qi * knj1 - ki * qnj1), 0.f);
        float r0v = a0, r1v = a1;
        float keep0 = 0.f, keep1 = 0.f, sum8 = 0.f;
        #pragma unroll
        for (int it = 0; it < 8; ++it) {
            float c; int cj;
            if (r0v >= r1v) { c = r0v; cj = lane; } else { c = r1v; cj = lane + 32; }
            #pragma unroll
            for (int off = 16; off; off >>= 1) {
                float oc = __shfl_xor_sync(0xffffffffu, c, off);
                int   oj = __shfl_xor_sync(0xffffffffu, cj, off);
                if (oc > c || (oc == c && oj < cj)) { c = oc; cj = oj; }
            }
            sum8 += c;
            if (cj == lane)           { keep0 = 1.f; r0v = -1.f; }
            else if (cj == lane + 32) { keep1 = 1.f; r1v = -1.f; }
        }
        float contrib = keep0 * a0 * vj0 + keep1 * a1 * vj1;
        #pragma unroll
        for (int off = 16; off; off >>= 1) contrib += __shfl_xor_sync(0xffffffffu, contrib, off);
        if (lane == 0) av[i] = contrib / fmaxf(sum8, EPSF);
    }
    __syncthreads();

    // z = leaky(Av @ Wagg + bagg)
    if (tid < 64) {
        float acc = bagg[tid];
        #pragma unroll 8
        for (int e = 0; e < 64; ++e) acc = fmaf(av[e], Wagg[e * 64 + tid], acc);
        g_z[(size_t)n * 64 + tid] = leaky(acc);
    }
}

// ============================================================
// Kernel 3: overlap-average gather + decoder GEMM (64 rows/block)
// out = u @ W_dec + b_dec,  u = avg of covering z patches
// ============================================================
#define DEC_SMEM (131072 + 64*66*8)   // Ws [64][512] + us2 [64][66] u64 = 164864 B

__global__ void __launch_bounds__(256, 1)
dec_kernel(const float* __restrict__ Wd, const float* __restrict__ bd,
           float* __restrict__ out)
{
    extern __shared__ unsigned char sm[];
    float* Ws = (float*)sm;                                   // [64][512]
    ull (*us2)[66] = reinterpret_cast<ull(*)[66]>(sm + 131072);

    const int tid = threadIdx.x;
    const int row0 = blockIdx.x * 64;

    // stage W_dec (128 KB) into smem
    {
        const float4* src = (const float4*)Wd;
        float4* dst = (float4*)Ws;
        #pragma unroll
        for (int i = 0; i < 32; ++i) dst[tid + i * 256] = src[tid + i * 256];
    }
    // compute u rows (dup-packed)
    {
        int d = tid & 63;
        #pragma unroll
        for (int i = 0; i < 16; ++i) {
            int rloc = (tid >> 6) + 4 * i;
            int rg = row0 + rloc;
            int bb = rg >> 12;
            int l  = rg & 4095;
            int phi = l >> 3;        if (phi > HP - 1) phi = HP - 1;
            int plo = (l - 8) >> 3;  if (plo < 0) plo = 0;
            float s = g_z[((size_t)bb * HP + plo) * 64 + d];
            float scale = 1.0f;
            if (phi > plo) { s += g_z[((size_t)bb * HP + phi) * 64 + d]; scale = 0.5f; }
            float u = s * scale;
            us2[rloc][d] = pack2(u, u);
        }
    }
    __syncthreads();

    const int w = tid >> 5, lane = tid & 31;
    const int rb = w * 8;

    #pragma unroll
    for (int ch = 0; ch < 2; ++ch) {
        const int cbd = ch * 256 + lane * 8;
        ull acc[8][4];
        {
            const ull* bp = (const ull*)(bd + cbd);
            ull b0 = bp[0], b1 = bp[1], b2 = bp[2], b3 = bp[3];
            #pragma unroll
            for (int r = 0; r < 8; ++r) { acc[r][0]=b0; acc[r][1]=b1; acc[r][2]=b2; acc[r][3]=b3; }
        }
        #pragma unroll 8
        for (int k = 0; k < 64; k += 2) {
            ulonglong2 bA0 = *(const ulonglong2*)&Ws[k * 512 + cbd];
            ulonglong2 bA1 = *(const ulonglong2*)&Ws[k * 512 + cbd + 4];
            ulonglong2 bB0 = *(const ulonglong2*)&Ws[(k + 1) * 512 + cbd];
            ulonglong2 bB1 = *(const ulonglong2*)&Ws[(k + 1) * 512 + cbd + 4];
            #pragma unroll
            for (int r = 0; r < 8; ++r) {
                ulonglong2 a = *(const ulonglong2*)&us2[rb + r][k];
                acc[r][0] = ffma2(a.x, bA0.x, acc[r][0]);
                acc[r][1] = ffma2(a.x, bA0.y, acc[r][1]);
                acc[r][2] = ffma2(a.x, bA1.x, acc[r][2]);
                acc[r][3] = ffma2(a.x, bA1.y, acc[r][3]);
                acc[r][0] = ffma2(a.y, bB0.x, acc[r][0]);
                acc[r][1] = ffma2(a.y, bB0.y, acc[r][1]);
                acc[r][2] = ffma2(a.y, bB1.x, acc[r][2]);
                acc[r][3] = ffma2(a.y, bB1.y, acc[r][3]);
            }
        }
        #pragma unroll
        for (int r = 0; r < 8; ++r) {
            ulonglong2 s0, s1;
            s0.x = acc[r][0]; s0.y = acc[r][1];
            s1.x = acc[r][2]; s1.y = acc[r][3];
            float* op = out + (size_t)(row0 + rb + r) * 512 + cbd;
            *(ulonglong2*)(op)     = s0;
            *(ulonglong2*)(op + 4) = s1;
        }
    }
}

// ============================================================
extern "C" void kernel_launch(void* const* d_in, const int* in_sizes, int n_in,
                              void* d_out, int out_size)
{
    const float* X    = (const float*)d_in[0];
    const float* We1  = (const float*)d_in[1];
    const float* be1  = (const float*)d_in[2];
    const float* We2  = (const float*)d_in[3];
    const float* be2  = (const float*)d_in[4];
    const float* Wq   = (const float*)d_in[5];
    const float* Wk   = (const float*)d_in[6];
    const float* Wv   = (const float*)d_in[7];
    const float* Wagg = (const float*)d_in[8];
    const float* bagg = (const float*)d_in[9];
    const float* Wd   = (const float*)d_in[10];
    const float* bd   = (const float*)d_in[11];
    float* out = (float*)d_out;

    cudaFuncSetAttribute(enc_kernel, cudaFuncAttributeMaxDynamicSharedMemorySize, ENC_SMEM);
    cudaFuncSetAttribute(dec_kernel, cudaFuncAttributeMaxDynamicSharedMemorySize, DEC_SMEM);

    enc_kernel<<<NR / 64, 256, ENC_SMEM>>>(X, We1, be1, We2, be2);
    attn_kernel<<<NP, 128>>>(Wq, Wk, Wv, Wagg, bagg);
    dec_kernel<<<NR / 64, 256, DEC_SMEM>>>(Wd, bd, out);
}

// round 7
// speedup vs baseline: 1.0010x; 1.0010x over previous
#include <cuda_runtime.h>
#include <cuda_bf16.h>

typedef unsigned long long ull;

// ---------------- constants ----------------
#define BB     16
#define LL     4096
#define DD     512
#define H1     256
#define DE     64
#define PATCH  16
#define STRIDE 8
#define HP     511            // patches per batch
#define NP     (BB*HP)        // 8176 patch rows
#define NR     (BB*LL)        // 65536 token rows
#define EPSF   1e-8f

// ---------------- scratch (device globals; no allocation) ----------------
__device__ float g_Xe[(size_t)NR * DE];   // encoded tokens (16.8 MB)
__device__ float g_z [(size_t)NP * DE];   // per-patch aggregated z (2.1 MB)

// ---------------- f32x2 helpers ----------------
__device__ __forceinline__ ull ffma2(ull a, ull b, ull c) {
    ull d;
    asm("fma.rn.f32x2 %0, %1, %2, %3;" : "=l"(d) : "l"(a), "l"(b), "l"(c));
    return d;
}
__device__ __forceinline__ ull pack2(float lo, float hi) {
    ull r;
    asm("mov.b64 %0, {%1, %2};" : "=l"(r) : "f"(lo), "f"(hi));
    return r;
}
__device__ __forceinline__ float2 unpack2(ull v) {
    float2 f;
    asm("mov.b64 {%0, %1}, %2;" : "=f"(f.x), "=f"(f.y) : "l"(v));
    return f;
}
__device__ __forceinline__ float leaky(float x) { return x > 0.f ? x : 0.01f * x; }

// ============================================================
// Kernel 1: fused encoder.  64 rows/block, 256 threads.
// stage1: H = leaky(X @ W1 + b1)   (64 x 256, K=512)
// stage2: Xe = H @ W2 + b2         (64 x 64,  K=256)
// ============================================================
#define ENC_SMEM (9216 + 16384 + 66560 + 4096)   // Xs2 | Ws1 | Hs | W2s = 96256 B

__global__ void __launch_bounds__(256, 2)
enc_kernel(const float* __restrict__ X,
           const float* __restrict__ We1, const float* __restrict__ be1,
           const float* __restrict__ We2, const float* __restrict__ be2)
{
    extern __shared__ unsigned char sm[];
    ull   (*Xs2)[18]  = reinterpret_cast<ull(*)[18]>(sm);            // dup-packed X tile [64][16]
    float (*Ws1)[256] = reinterpret_cast<float(*)[256]>(sm + 9216);  // W1 tile [16][256]
    float (*Hs)[260]  = reinterpret_cast<float(*)[260]>(sm + 25600); // hidden [64][256] padded
    float (*W2s)[64]  = reinterpret_cast<float(*)[64]>(sm + 92160);  // W2 tile [16][64]

    const int tid  = threadIdx.x;
    const int w    = tid >> 5;
    const int lane = tid & 31;
    const int r0   = blockIdx.x * 64;
    const int rb   = w * 8;        // 8 warps x 8 rows
    const int cb   = lane * 8;     // 32 lanes x 8 cols = 256

    ull acc[8][4];
    #pragma unroll
    for (int r = 0; r < 8; ++r)
        #pragma unroll
        for (int p = 0; p < 4; ++p) acc[r][p] = 0ull;

    for (int kt = 0; kt < DD; kt += 16) {
        // load X tile (64 rows x 16 k), duplicated into u64 pairs
        {
            int row = tid >> 2, q = tid & 3;
            float4 g = *(const float4*)(X + (size_t)(r0 + row) * DD + kt + q * 4);
            Xs2[row][q * 4 + 0] = pack2(g.x, g.x);
            Xs2[row][q * 4 + 1] = pack2(g.y, g.y);
            Xs2[row][q * 4 + 2] = pack2(g.z, g.z);
            Xs2[row][q * 4 + 3] = pack2(g.w, g.w);
        }
        // load W1 tile (16 x 256)
        {
            const float4* src = (const float4*)(We1 + (size_t)kt * H1);
            float4* dst = (float4*)Ws1;
            #pragma unroll
            for (int i = 0; i < 4; ++i) dst[tid + i * 256] = src[tid + i * 256];
        }
        __syncthreads();

        #pragma unroll
        for (int k = 0; k < 16; k += 2) {
            ulonglong2 bA0 = *(const ulonglong2*)&Ws1[k][cb];
            ulonglong2 bA1 = *(const ulonglong2*)&Ws1[k][cb + 4];
            ulonglong2 bB0 = *(const ulonglong2*)&Ws1[k + 1][cb];
            ulonglong2 bB1 = *(const ulonglong2*)&Ws1[k + 1][cb + 4];
            #pragma unroll
            for (int r = 0; r < 8; ++r) {
                ulonglong2 a = *(const ulonglong2*)&Xs2[rb + r][k];
                acc[r][0] = ffma2(a.x, bA0.x, acc[r][0]);
                acc[r][1] = ffma2(a.x, bA0.y, acc[r][1]);
                acc[r][2] = ffma2(a.x, bA1.x, acc[r][2]);
                acc[r][3] = ffma2(a.x, bA1.y, acc[r][3]);
                acc[r][0] = ffma2(a.y, bB0.x, acc[r][0]);
                acc[r][1] = ffma2(a.y, bB0.y, acc[r][1]);
                acc[r][2] = ffma2(a.y, bB1.x, acc[r][2]);
                acc[r][3] = ffma2(a.y, bB1.y, acc[r][3]);
            }
        }
        __syncthreads();
    }

    // epilogue stage1: bias + leaky -> Hs
    #pragma unroll
    for (int p = 0; p < 4; ++p) {
        int c = cb + p * 2;
        float bx = be1[c], by = be1[c + 1];
        #pragma unroll
        for (int r = 0; r < 8; ++r) {
            float2 v = unpack2(acc[r][p]);
            float x0 = leaky(v.x + bx);
            float x1 = leaky(v.y + by);
            *(float2*)&Hs[rb + r][c] = make_float2(x0, x1);
        }
    }

    // stage2: Xe = Hs @ W2 + b2   (each warp: its 8 rows x all 64 cols, 2 cols/lane)
    const int c2 = lane * 2;
    ull acc2[8];
    {
        float b0 = be2[c2], b1f = be2[c2 + 1];
        #pragma unroll
        for (int r = 0; r < 8; ++r) acc2[r] = pack2(b0, b1f);
    }
    for (int kt = 0; kt < H1; kt += 16) {
        ((float4*)W2s)[tid] = ((const float4*)(We2 + (size_t)kt * DE))[tid];
        __syncthreads();
        #pragma unroll
        for (int k = 0; k < 16; k += 2) {
            ull w0 = *(const ull*)&W2s[k][c2];
            ull w1 = *(const ull*)&W2s[k + 1][c2];
            #pragma unroll
            for (int r = 0; r < 8; ++r) {
                float2 a = *(const float2*)&Hs[rb + r][kt + k];
                acc2[r] = ffma2(pack2(a.x, a.x), w0, acc2[r]);
                acc2[r] = ffma2(pack2(a.y, a.y), w1, acc2[r]);
            }
        }
        __syncthreads();
    }
    #pragma unroll
    for (int r = 0; r < 8; ++r)
        *(ull*)&g_Xe[(size_t)(r0 + rb + r) * DE + c2] = acc2[r];
}

// ============================================================
// Kernel 2: patch attention.  One block (128 thr) per patch row.
// ============================================================
__global__ void __launch_bounds__(128)
attn_kernel(const float* __restrict__ Wq, const float* __restrict__ Wk,
            const float* __restrict__ Wv, const float* __restrict__ Wagg,
            const float* __restrict__ bagg)
{
    __shared__ float pp[64], sq[64], sk[64], sv[64], av[64], tmp[128];
    __shared__ float sinvq, sinvk;

    const int n = blockIdx.x;
    const int b = n / HP;
    const int p = n % HP;
    const int tid = threadIdx.x;

    // patch mean over 16 tokens
    {
        int d = tid & 63, half = tid >> 6;
        const float* base = g_Xe + ((size_t)b * LL + p * STRIDE + half * 8) * DE + d;
        float s = 0.f;
        #pragma unroll
        for (int t = 0; t < 8; ++t) s += base[t * DE];
        tmp[tid] = s;
    }
    __syncthreads();
    if (tid < 64) pp[tid] = (tmp[tid] + tmp[tid + 64]) * 0.0625f;
    __syncthreads();

    // q, k, v
    if (tid < 64) {
        float aq = 0.f, ak = 0.f, avv = 0.f;
        #pragma unroll 8
        for (int e = 0; e < 64; ++e) {
            float x = pp[e];
            aq  = fmaf(x, Wq[e * 64 + tid], aq);
            ak  = fmaf(x, Wk[e * 64 + tid], ak);
            avv = fmaf(x, Wv[e * 64 + tid], avv);
        }
        sq[tid] = aq; sk[tid] = ak; sv[tid] = avv;
    }
    __syncthreads();

    // norms
    if (tid < 64) {
        int lane = tid & 31;
        bool isQ = tid < 32;
        const float* arr = isQ ? sq : sk;
        float s2 = arr[lane] * arr[lane] + arr[lane + 32] * arr[lane + 32];
        #pragma unroll
        for (int off = 16; off; off >>= 1) s2 += __shfl_xor_sync(0xffffffffu, s2, off);
        float inv = 1.0f / (sqrtf(s2) + EPSF);
        if (lane == 0) { if (isQ) sinvq = inv; else sinvk = inv; }
    }
    __syncthreads();
    if (tid < 64) { sq[tid] *= sinvq; sk[tid] *= sinvk; }
    __syncthreads();

    // attention rows: warp w handles rows w*16 .. w*16+15, each lane owns cols (lane, lane+32)
    const int w = tid >> 5, lane = tid & 31;
    const float knj0 = sk[lane], knj1 = sk[lane + 32];
    const float qnj0 = sq[lane], qnj1 = sq[lane + 32];
    const float vj0  = sv[lane], vj1  = sv[lane + 32];

    for (int ii = 0; ii < 16; ++ii) {
        int i = w * 16 + ii;
        float qi = sq[i], ki = sk[i];
        float a0 = fmaxf(tanhf(qi * knj0 - ki * qnj0), 0.f);
        float a1 = fmaxf(tanhf(qi * knj1 - ki * qnj1), 0.f);
        float r0v = a0, r1v = a1;
        float keep0 = 0.f, keep1 = 0.f, sum8 = 0.f;
        #pragma unroll
        for (int it = 0; it < 8; ++it) {
            float c; int cj;
            if (r0v >= r1v) { c = r0v; cj = lane; } else { c = r1v; cj = lane + 32; }
            #pragma unroll
            for (int off = 16; off; off >>= 1) {
                float oc = __shfl_xor_sync(0xffffffffu, c, off);
                int   oj = __shfl_xor_sync(0xffffffffu, cj, off);
                if (oc > c || (oc == c && oj < cj)) { c = oc; cj = oj; }
            }
            sum8 += c;
            if (cj == lane)           { keep0 = 1.f; r0v = -1.f; }
            else if (cj == lane + 32) { keep1 = 1.f; r1v = -1.f; }
        }
        float contrib = keep0 * a0 * vj0 + keep1 * a1 * vj1;
        #pragma unroll
        for (int off = 16; off; off >>= 1) contrib += __shfl_xor_sync(0xffffffffu, contrib, off);
        if (lane == 0) av[i] = contrib / fmaxf(sum8, EPSF);
    }
    __syncthreads();

    // z = leaky(Av @ Wagg + bagg)
    if (tid < 64) {
        float acc = bagg[tid];
        #pragma unroll 8
        for (int e = 0; e < 64; ++e) acc = fmaf(av[e], Wagg[e * 64 + tid], acc);
        g_z[(size_t)n * 64 + tid] = leaky(acc);
    }
}

// ============================================================
// Kernel 3: overlap-average gather + decoder GEMM (64 rows/block)
// out = u @ W_dec + b_dec,  u = avg of covering z patches
// ============================================================
#define DEC_SMEM (131072 + 64*66*8)   // Ws [64][512] + us2 [64][66] u64 = 164864 B

__global__ void __launch_bounds__(256, 1)
dec_kernel(const float* __restrict__ Wd, const float* __restrict__ bd,
           float* __restrict__ out)
{
    extern __shared__ unsigned char sm[];
    float* Ws = (float*)sm;                                   // [64][512]
    ull (*us2)[66] = reinterpret_cast<ull(*)[66]>(sm + 131072);

    const int tid = threadIdx.x;
    const int row0 = blockIdx.x * 64;

    // stage W_dec (128 KB) into smem
    {
        const float4* src = (const float4*)Wd;
        float4* dst = (float4*)Ws;
        #pragma unroll
        for (int i = 0; i < 32; ++i) dst[tid + i * 256] = src[tid + i * 256];
    }
    // compute u rows (dup-packed)
    {
        int d = tid & 63;
        #pragma unroll
        for (int i = 0; i < 16; ++i) {
            int rloc = (tid >> 6) + 4 * i;
            int rg = row0 + rloc;
            int bb = rg >> 12;
            int l  = rg & 4095;
            int phi = l >> 3;        if (phi > HP - 1) phi = HP - 1;
            int plo = (l - 8) >> 3;  if (plo < 0) plo = 0;
            float s = g_z[((size_t)bb * HP + plo) * 64 + d];
            float scale = 1.0f;
            if (phi > plo) { s += g_z[((size_t)bb * HP + phi) * 64 + d]; scale = 0.5f; }
            float u = s * scale;
            us2[rloc][d] = pack2(u, u);
        }
    }
    __syncthreads();

    const int w = tid >> 5, lane = tid & 31;
    const int rb = w * 8;

    #pragma unroll
    for (int ch = 0; ch < 2; ++ch) {
        const int cbd = ch * 256 + lane * 8;
        ull acc[8][4];
        {
            const ull* bp = (const ull*)(bd + cbd);
            ull b0 = bp[0], b1 = bp[1], b2 = bp[2], b3 = bp[3];
            #pragma unroll
            for (int r = 0; r < 8; ++r) { acc[r][0]=b0; acc[r][1]=b1; acc[r][2]=b2; acc[r][3]=b3; }
        }
        #pragma unroll 8
        for (int k = 0; k < 64; k += 2) {
            ulonglong2 bA0 = *(const ulonglong2*)&Ws[k * 512 + cbd];
            ulonglong2 bA1 = *(const ulonglong2*)&Ws[k * 512 + cbd + 4];
            ulonglong2 bB0 = *(const ulonglong2*)&Ws[(k + 1) * 512 + cbd];
            ulonglong2 bB1 = *(const ulonglong2*)&Ws[(k + 1) * 512 + cbd + 4];
            #pragma unroll
            for (int r = 0; r < 8; ++r) {
                ulonglong2 a = *(const ulonglong2*)&us2[rb + r][k];
                acc[r][0] = ffma2(a.x, bA0.x, acc[r][0]);
                acc[r][1] = ffma2(a.x, bA0.y, acc[r][1]);
                acc[r][2] = ffma2(a.x, bA1.x, acc[r][2]);
                acc[r][3] = ffma2(a.x, bA1.y, acc[r][3]);
                acc[r][0] = ffma2(a.y, bB0.x, acc[r][0]);
                acc[r][1] = ffma2(a.y, bB0.y, acc[r][1]);
                acc[r][2] = ffma2(a.y, bB1.x, acc[r][2]);
                acc[r][3] = ffma2(a.y, bB1.y, acc[r][3]);
            }
        }
        #pragma unroll
        for (int r = 0; r < 8; ++r) {
            ulonglong2 s0, s1;
            s0.x = acc[r][0]; s0.y = acc[r][1];
            s1.x = acc[r][2]; s1.y = acc[r][3];
            float* op = out + (size_t)(row0 + rb + r) * 512 + cbd;
            *(ulonglong2*)(op)     = s0;
            *(ulonglong2*)(op + 4) = s1;
        }
    }
}

// ============================================================
extern "C" void kernel_launch(void* const* d_in, const int* in_sizes, int n_in,
                              void* d_out, int out_size)
{
    const float* X    = (const float*)d_in[0];
    const float* We1  = (const float*)d_in[1];
    const float* be1  = (const float*)d_in[2];
    const float* We2  = (const float*)d_in[3];
    const float* be2  = (const float*)d_in[4];
    const float* Wq   = (const float*)d_in[5];
    const float* Wk   = (const float*)d_in[6];
    const float* Wv   = (const float*)d_in[7];
    const float* Wagg = (const float*)d_in[8];
    const float* bagg = (const float*)d_in[9];
    const float* Wd   = (const float*)d_in[10];
    const float* bd   = (const float*)d_in[11];
    float* out = (float*)d_out;

    cudaFuncSetAttribute(enc_kernel, cudaFuncAttributeMaxDynamicSharedMemorySize, ENC_SMEM);
    cudaFuncSetAttribute(dec_kernel, cudaFuncAttributeMaxDynamicSharedMemorySize, DEC_SMEM);

    enc_kernel<<<NR / 64, 256, ENC_SMEM>>>(X, We1, be1, We2, be2);
    attn_kernel<<<NP, 128>>>(Wq, Wk, Wv, Wagg, bagg);
    dec_kernel<<<NR / 64, 256, DEC_SMEM>>>(Wd, bd, out);
}

// round 8
// speedup vs baseline: 1.4146x; 1.4133x over previous
#include <cuda_runtime.h>
#include <cuda_bf16.h>

typedef unsigned long long ull;

// ---------------- constants ----------------
#define BB     16
#define LL     4096
#define DD     512
#define H1     256
#define DE     64
#define STRIDE 8
#define HP     511            // patches per batch
#define NP     (BB*HP)        // 8176 patch rows
#define NR     (BB*LL)        // 65536 token rows
#define NG     (NR/8)         // 8192 groups of 8 tokens
#define EPSF   1e-8f

// ---------------- scratch (device globals; no allocation) ----------------
__device__ float g_G [(size_t)NG * H1];   // 8-token group sums of H (8 MB)
__device__ float g_qn[(size_t)NP * DE];
__device__ float g_kn[(size_t)NP * DE];
__device__ float g_v [(size_t)NP * DE];
__device__ float g_z [(size_t)NP * DE];

// ---------------- helpers ----------------
__device__ __forceinline__ ull ffma2(ull a, ull b, ull c) {
    ull d;
    asm("fma.rn.f32x2 %0, %1, %2, %3;" : "=l"(d) : "l"(a), "l"(b), "l"(c));
    return d;
}
__device__ __forceinline__ ull pack2(float lo, float hi) {
    ull r;
    asm("mov.b64 %0, {%1, %2};" : "=l"(r) : "f"(lo), "f"(hi));
    return r;
}
__device__ __forceinline__ float2 unpack2(ull v) {
    float2 f;
    asm("mov.b64 {%0, %1}, %2;" : "=f"(f.x), "=f"(f.y) : "l"(v));
    return f;
}
__device__ __forceinline__ float leaky(float x) { return x > 0.f ? x : 0.01f * x; }

// ============================================================
// Kernel 1: encoder stage1 + 8-row group sums.
// H = leaky(X @ W1 + b1); g_G[g][c] = sum over 8 rows of group g.
// 64 rows/block, 256 threads, 8 warps x 8 rows.
// Lane owns cols {lane*4..+3} and {128+lane*4..+3}  (16B stride, conflict-free)
// ============================================================
#define ENC_SMEM (9216 + 16384)   // Xs2 [64][18] ull | Ws1 [16][256] f32

__global__ void __launch_bounds__(256, 2)
enc1_kernel(const float* __restrict__ X,
            const float* __restrict__ We1, const float* __restrict__ be1)
{
    extern __shared__ unsigned char sm[];
    ull   (*Xs2)[18]  = reinterpret_cast<ull(*)[18]>(sm);
    float (*Ws1)[256] = reinterpret_cast<float(*)[256]>(sm + 9216);

    const int tid  = threadIdx.x;
    const int w    = tid >> 5;
    const int lane = tid & 31;
    const int r0   = blockIdx.x * 64;
    const int rb   = w * 8;
    const int c4   = lane * 4;

    ull acc[8][4];
    #pragma unroll
    for (int r = 0; r < 8; ++r)
        #pragma unroll
        for (int p = 0; p < 4; ++p) acc[r][p] = 0ull;

    const int xrow = tid >> 2, xq = tid & 3;

    // prefetch tile 0
    float4 xg = *(const float4*)(X + (size_t)(r0 + xrow) * DD + xq * 4);
    float4 wg0 = ((const float4*)We1)[tid];
    float4 wg1 = ((const float4*)We1)[tid + 256];
    float4 wg2 = ((const float4*)We1)[tid + 512];
    float4 wg3 = ((const float4*)We1)[tid + 768];

    for (int kt = 0; kt < DD; kt += 16) {
        // stage current tile into smem
        Xs2[xrow][xq * 4 + 0] = pack2(xg.x, xg.x);
        Xs2[xrow][xq * 4 + 1] = pack2(xg.y, xg.y);
        Xs2[xrow][xq * 4 + 2] = pack2(xg.z, xg.z);
        Xs2[xrow][xq * 4 + 3] = pack2(xg.w, xg.w);
        {
            float4* dst = (float4*)Ws1;
            dst[tid]       = wg0;
            dst[tid + 256] = wg1;
            dst[tid + 512] = wg2;
            dst[tid + 768] = wg3;
        }
        __syncthreads();

        // prefetch next tile
        if (kt + 16 < DD) {
            xg = *(const float4*)(X + (size_t)(r0 + xrow) * DD + (kt + 16) + xq * 4);
            const float4* src = (const float4*)(We1 + (size_t)(kt + 16) * H1);
            wg0 = src[tid]; wg1 = src[tid + 256]; wg2 = src[tid + 512]; wg3 = src[tid + 768];
        }

        #pragma unroll
        for (int k = 0; k < 16; k += 2) {
            ulonglong2 bA0 = *(const ulonglong2*)&Ws1[k][c4];
            ulonglong2 bA1 = *(const ulonglong2*)&Ws1[k][128 + c4];
            ulonglong2 bB0 = *(const ulonglong2*)&Ws1[k + 1][c4];
            ulonglong2 bB1 = *(const ulonglong2*)&Ws1[k + 1][128 + c4];
            #pragma unroll
            for (int r = 0; r < 8; ++r) {
                ulonglong2 a = *(const ulonglong2*)&Xs2[rb + r][k];
                acc[r][0] = ffma2(a.x, bA0.x, acc[r][0]);
                acc[r][1] = ffma2(a.x, bA0.y, acc[r][1]);
                acc[r][2] = ffma2(a.x, bA1.x, acc[r][2]);
                acc[r][3] = ffma2(a.x, bA1.y, acc[r][3]);
                acc[r][0] = ffma2(a.y, bB0.x, acc[r][0]);
                acc[r][1] = ffma2(a.y, bB0.y, acc[r][1]);
                acc[r][2] = ffma2(a.y, bB1.x, acc[r][2]);
                acc[r][3] = ffma2(a.y, bB1.y, acc[r][3]);
            }
        }
        __syncthreads();
    }

    // epilogue: bias + leaky + 8-row group sum (all in registers)
    float4 blo = *(const float4*)(be1 + c4);
    float4 bhi = *(const float4*)(be1 + 128 + c4);
    float s0=0,s1=0,s2=0,s3=0,s4=0,s5=0,s6=0,s7=0;
    #pragma unroll
    for (int r = 0; r < 8; ++r) {
        float2 v;
        v = unpack2(acc[r][0]); s0 += leaky(v.x + blo.x); s1 += leaky(v.y + blo.y);
        v = unpack2(acc[r][1]); s2 += leaky(v.x + blo.z); s3 += leaky(v.y + blo.w);
        v = unpack2(acc[r][2]); s4 += leaky(v.x + bhi.x); s5 += leaky(v.y + bhi.y);
        v = unpack2(acc[r][3]); s6 += leaky(v.x + bhi.z); s7 += leaky(v.y + bhi.w);
    }
    const int g = blockIdx.x * 8 + w;   // warp's 8 rows == one token-group
    *(float4*)(g_G + (size_t)g * H1 + c4)       = make_float4(s0, s1, s2, s3);
    *(float4*)(g_G + (size_t)g * H1 + 128 + c4) = make_float4(s4, s5, s6, s7);
}

// ============================================================
// Kernel 2: per-patch pp = ((G[p]+G[p+1])/16) @ W2 + b2, then
// q,k,v = pp @ Wq/Wk/Wv, normalize q,k.  64 patches/block, 256 thr.
// thread t: patch i = t>>2, col group dg = t&3 (16 cols each).
// ============================================================
#define SROW 260
#define PROW 68
#define PP_SMEM (64*SROW*4 + 256*64*4 + 64*PROW*4)   // 66560 + 65536 + 17408 = 149504

__global__ void __launch_bounds__(256)
ppqkv_kernel(const float* __restrict__ W2, const float* __restrict__ b2,
             const float* __restrict__ Wq, const float* __restrict__ Wk,
             const float* __restrict__ Wv)
{
    extern __shared__ unsigned char sm[];
    float* S   = (float*)sm;                       // [64][260]
    float* W2s = (float*)(sm + 64*SROW*4);         // [256][64]
    float* PPs = (float*)(sm + 64*SROW*4 + 65536); // [64][68]
    float* Wqs = (float*)sm;                       // phase B reuse of S region
    float* Wks = (float*)(sm + 16384);
    float* Wvs = (float*)(sm + 32768);

    const int tid = threadIdx.x;
    const int blk = blockIdx.x;

    // stage S = (G[p] + G[p+1]) / 16
    for (int idx = tid; idx < 64 * 64; idx += 256) {
        int i = idx >> 6, e4 = (idx & 63) * 4;
        int n = blk * 64 + i;
        float4 v = make_float4(0.f, 0.f, 0.f, 0.f);
        if (n < NP) {
            int b = n / HP, p = n - b * HP;
            const float* g0 = g_G + ((size_t)b * 512 + p) * H1 + e4;
            float4 a = *(const float4*)g0;
            float4 c = *(const float4*)(g0 + H1);
            v = make_float4((a.x + c.x) * 0.0625f, (a.y + c.y) * 0.0625f,
                            (a.z + c.z) * 0.0625f, (a.w + c.w) * 0.0625f);
        }
        *(float4*)&S[i * SROW + e4] = v;
    }
    // stage W2
    for (int idx = tid; idx < 4096; idx += 256)
        ((float4*)W2s)[idx] = ((const float4*)W2)[idx];
    __syncthreads();

    const int i  = tid >> 2;
    const int d0 = (tid & 3) * 16;

    // phase A: PP[i][d0..d0+15]
    float accA[16];
    {
        const float4* bp = (const float4*)(b2 + d0);
        #pragma unroll
        for (int j = 0; j < 4; ++j) {
            float4 b4 = bp[j];
            accA[j*4+0]=b4.x; accA[j*4+1]=b4.y; accA[j*4+2]=b4.z; accA[j*4+3]=b4.w;
        }
    }
    for (int e = 0; e < H1; ++e) {
        float s = S[i * SROW + e];
        const float4* wr = (const float4*)(W2s + e * 64 + d0);
        #pragma unroll
        for (int j = 0; j < 4; ++j) {
            float4 w4 = wr[j];
            accA[j*4+0] = fmaf(s, w4.x, accA[j*4+0]);
            accA[j*4+1] = fmaf(s, w4.y, accA[j*4+1]);
            accA[j*4+2] = fmaf(s, w4.z, accA[j*4+2]);
            accA[j*4+3] = fmaf(s, w4.w, accA[j*4+3]);
        }
    }
    #pragma unroll
    for (int j = 0; j < 4; ++j)
        *(float4*)&PPs[i * PROW + d0 + j * 4] =
            make_float4(accA[j*4+0], accA[j*4+1], accA[j*4+2], accA[j*4+3]);
    __syncthreads();

    // stage Wq/Wk/Wv over the S region
    for (int idx = tid; idx < 1024; idx += 256) {
        ((float4*)Wqs)[idx] = ((const float4*)Wq)[idx];
        ((float4*)Wks)[idx] = ((const float4*)Wk)[idx];
        ((float4*)Wvs)[idx] = ((const float4*)Wv)[idx];
    }
    __syncthreads();

    // phase B: q,k,v for 16 cols
    float q[16], kk[16], vv[16];
    #pragma unroll
    for (int j = 0; j < 16; ++j) { q[j] = 0.f; kk[j] = 0.f; vv[j] = 0.f; }
    for (int e = 0; e < 64; ++e) {
        float p = PPs[i * PROW + e];
        const float4* wq = (const float4*)(Wqs + e * 64 + d0);
        const float4* wk = (const float4*)(Wks + e * 64 + d0);
        const float4* wv = (const float4*)(Wvs + e * 64 + d0);
        #pragma unroll
        for (int j = 0; j < 4; ++j) {
            float4 a = wq[j], b = wk[j], c = wv[j];
            q [j*4+0]=fmaf(p,a.x,q [j*4+0]); q [j*4+1]=fmaf(p,a.y,q [j*4+1]);
            q [j*4+2]=fmaf(p,a.z,q [j*4+2]); q [j*4+3]=fmaf(p,a.w,q [j*4+3]);
            kk[j*4+0]=fmaf(p,b.x,kk[j*4+0]); kk[j*4+1]=fmaf(p,b.y,kk[j*4+1]);
            kk[j*4+2]=fmaf(p,b.z,kk[j*4+2]); kk[j*4+3]=fmaf(p,b.w,kk[j*4+3]);
            vv[j*4+0]=fmaf(p,c.x,vv[j*4+0]); vv[j*4+1]=fmaf(p,c.y,vv[j*4+1]);
            vv[j*4+2]=fmaf(p,c.z,vv[j*4+2]); vv[j*4+3]=fmaf(p,c.w,vv[j*4+3]);
        }
    }
    // norms across the 4-thread quad
    float q2 = 0.f, k2 = 0.f;
    #pragma unroll
    for (int j = 0; j < 16; ++j) { q2 = fmaf(q[j], q[j], q2); k2 = fmaf(kk[j], kk[j], k2); }
    q2 += __shfl_xor_sync(0xffffffffu, q2, 1); q2 += __shfl_xor_sync(0xffffffffu, q2, 2);
    k2 += __shfl_xor_sync(0xffffffffu, k2, 1); k2 += __shfl_xor_sync(0xffffffffu, k2, 2);
    float invq = 1.0f / (sqrtf(q2) + EPSF);
    float invk = 1.0f / (sqrtf(k2) + EPSF);

    int n = blk * 64 + i;
    if (n < NP) {
        float* dq = g_qn + (size_t)n * 64 + d0;
        float* dk = g_kn + (size_t)n * 64 + d0;
        float* dv = g_v  + (size_t)n * 64 + d0;
        #pragma unroll
        for (int j = 0; j < 4; ++j) {
            *(float4*)(dq + j*4) = make_float4(q [j*4]*invq, q [j*4+1]*invq, q [j*4+2]*invq, q [j*4+3]*invq);
            *(float4*)(dk + j*4) = make_float4(kk[j*4]*invk, kk[j*4+1]*invk, kk[j*4+2]*invk, kk[j*4+3]*invk);
            *(float4*)(dv + j*4) = make_float4(vv[j*4],      vv[j*4+1],      vv[j*4+2],      vv[j*4+3]);
        }
    }
}

// ============================================================
// Kernel 3: attention. Warp per patch, 8 patches/block.
// top-8 per row via REDUX max on (value_hi26 | 63-j) keys.
// ============================================================
__global__ void __launch_bounds__(256)
attn_kernel(const float* __restrict__ Wagg, const float* __restrict__ bagg)
{
    __shared__ float sq[8][64], sk[8][64], sav[8][64];
    __shared__ float Wgs[64 * 64];

    const int tid = threadIdx.x;
    const int w = tid >> 5, lane = tid & 31;
    const int n = blockIdx.x * 8 + w;

    for (int idx = tid; idx < 1024; idx += 256)
        ((float4*)Wgs)[idx] = ((const float4*)Wagg)[idx];

    const size_t base = (size_t)n * 64;
    float q0 = g_qn[base + lane], q1 = g_qn[base + lane + 32];
    float k0 = g_kn[base + lane], k1 = g_kn[base + lane + 32];
    float v0 = g_v [base + lane], v1 = g_v [base + lane + 32];
    sq[w][lane] = q0; sq[w][lane + 32] = q1;
    sk[w][lane] = k0; sk[w][lane + 32] = k1;
    __syncthreads();   // Wgs staged + sq/sk visible

    for (int i = 0; i < 64; ++i) {
        float qi = sq[w][i], ki = sk[w][i];
        float a0 = fmaxf(tanhf(qi * k0 - ki * q0), 0.f);
        float a1 = fmaxf(tanhf(qi * k1 - ki * q1), 0.f);
        unsigned key0 = (__float_as_uint(a0) & 0xFFFFFFC0u) | (63u - (unsigned)lane);
        unsigned key1 = (__float_as_uint(a1) & 0xFFFFFFC0u) | (31u - (unsigned)lane);
        unsigned keep0 = 0u, keep1 = 0u;
        #pragma unroll
        for (int it = 0; it < 8; ++it) {
            unsigned mk = key0 > key1 ? key0 : key1;
            unsigned win = __reduce_max_sync(0xffffffffu, mk);
            if (key0 == win)      { keep0 = 1u; key0 = 0u; }
            else if (key1 == win) { keep1 = 1u; key1 = 0u; }
        }
        float fa0 = keep0 ? a0 : 0.f;
        float fa1 = keep1 ? a1 : 0.f;
        float contrib = fa0 * v0 + fa1 * v1;
        float suma    = fa0 + fa1;
        #pragma unroll
        for (int off = 16; off; off >>= 1) {
            contrib += __shfl_xor_sync(0xffffffffu, contrib, off);
            suma    += __shfl_xor_sync(0xffffffffu, suma, off);
        }
        if (lane == 0) sav[w][i] = contrib / fmaxf(suma, EPSF);
    }
    __syncwarp();

    // z = leaky(Av @ Wagg + bagg)
    float acc0 = bagg[lane], acc1 = bagg[lane + 32];
    #pragma unroll 8
    for (int e = 0; e < 64; ++e) {
        float ae = sav[w][e];
        acc0 = fmaf(ae, Wgs[e * 64 + lane],      acc0);
        acc1 = fmaf(ae, Wgs[e * 64 + lane + 32], acc1);
    }
    g_z[base + lane]      = leaky(acc0);
    g_z[base + lane + 32] = leaky(acc1);
}

// ============================================================
// Kernel 4: overlap-average gather + decoder GEMM (64 rows/block)
// Conflict-free column mapping: lane owns {c4..+3} and {128+c4..+3} per half.
// ============================================================
#define DEC_SMEM (131072 + 64*66*8)   // Ws [64][512] + us2 [64][66] u64

__global__ void __launch_bounds__(256, 1)
dec_kernel(const float* __restrict__ Wd, const float* __restrict__ bd,
           float* __restrict__ out)
{
    extern __shared__ unsigned char sm[];
    float* Ws = (float*)sm;                                   // [64][512]
    ull (*us2)[66] = reinterpret_cast<ull(*)[66]>(sm + 131072);

    const int tid = threadIdx.x;
    const int row0 = blockIdx.x * 64;

    {
        const float4* src = (const float4*)Wd;
        float4* dst = (float4*)Ws;
        #pragma unroll
        for (int i = 0; i < 32; ++i) dst[tid + i * 256] = src[tid + i * 256];
    }
    {
        int d = tid & 63;
        #pragma unroll
        for (int i = 0; i < 16; ++i) {
            int rloc = (tid >> 6) + 4 * i;
            int rg = row0 + rloc;
            int bb = rg >> 12;
            int l  = rg & 4095;
            int phi = l >> 3;        if (phi > HP - 1) phi = HP - 1;
            int plo = (l - 8) >> 3;  if (plo < 0) plo = 0;
            float s = g_z[((size_t)bb * HP + plo) * 64 + d];
            float scale = 1.0f;
            if (phi > plo) { s += g_z[((size_t)bb * HP + phi) * 64 + d]; scale = 0.5f; }
            float u = s * scale;
            us2[rloc][d] = pack2(u, u);
        }
    }
    __syncthreads();

    const int w = tid >> 5, lane = tid & 31;
    const int rb = w * 8;
    const int c4 = lane * 4;

    #pragma unroll
    for (int ch = 0; ch < 2; ++ch) {
        const int cb = ch * 256;
        ull acc[8][4];
        {
            float4 blo = *(const float4*)(bd + cb + c4);
            float4 bhi = *(const float4*)(bd + cb + 128 + c4);
            ull a0 = pack2(blo.x, blo.y), a1 = pack2(blo.z, blo.w);
            ull a2 = pack2(bhi.x, bhi.y), a3 = pack2(bhi.z, bhi.w);
            #pragma unroll
            for (int r = 0; r < 8; ++r) { acc[r][0]=a0; acc[r][1]=a1; acc[r][2]=a2; acc[r][3]=a3; }
        }
        #pragma unroll 8
        for (int k = 0; k < 64; k += 2) {
            ulonglong2 bA0 = *(const ulonglong2*)&Ws[k * 512 + cb + c4];
            ulonglong2 bA1 = *(const ulonglong2*)&Ws[k * 512 + cb + 128 + c4];
            ulonglong2 bB0 = *(const ulonglong2*)&Ws[(k + 1) * 512 + cb + c4];
            ulonglong2 bB1 = *(const ulonglong2*)&Ws[(k + 1) * 512 + cb + 128 + c4];
            #pragma unroll
            for (int r = 0; r < 8; ++r) {
                ulonglong2 a = *(const ulonglong2*)&us2[rb + r][k];
                acc[r][0] = ffma2(a.x, bA0.x, acc[r][0]);
                acc[r][1] = ffma2(a.x, bA0.y, acc[r][1]);
                acc[r][2] = ffma2(a.x, bA1.x, acc[r][2]);
                acc[r][3] = ffma2(a.x, bA1.y, acc[r][3]);
                acc[r][0] = ffma2(a.y, bB0.x, acc[r][0]);
                acc[r][1] = ffma2(a.y, bB0.y, acc[r][1]);
                acc[r][2] = ffma2(a.y, bB1.x, acc[r][2]);
                acc[r][3] = ffma2(a.y, bB1.y, acc[r][3]);
            }
        }
        #pragma unroll
        for (int r = 0; r < 8; ++r) {
            float* op = out + (size_t)(row0 + rb + r) * 512 + cb;
            ulonglong2 s0; s0.x = acc[r][0]; s0.y = acc[r][1];
            ulonglong2 s1; s1.x = acc[r][2]; s1.y = acc[r][3];
            *(ulonglong2*)(op + c4)       = s0;
            *(ulonglong2*)(op + 128 + c4) = s1;
        }
    }
}

// ============================================================
extern "C" void kernel_launch(void* const* d_in, const int* in_sizes, int n_in,
                              void* d_out, int out_size)
{
    const float* X    = (const float*)d_in[0];
    const float* We1  = (const float*)d_in[1];
    const float* be1  = (const float*)d_in[2];
    const float* We2  = (const float*)d_in[3];
    const float* be2  = (const float*)d_in[4];
    const float* Wq   = (const float*)d_in[5];
    const float* Wk   = (const float*)d_in[6];
    const float* Wv   = (const float*)d_in[7];
    const float* Wagg = (const float*)d_in[8];
    const float* bagg = (const float*)d_in[9];
    const float* Wd   = (const float*)d_in[10];
    const float* bd   = (const float*)d_in[11];
    float* out = (float*)d_out;

    cudaFuncSetAttribute(enc1_kernel,  cudaFuncAttributeMaxDynamicSharedMemorySize, ENC_SMEM);
    cudaFuncSetAttribute(ppqkv_kernel, cudaFuncAttributeMaxDynamicSharedMemorySize, PP_SMEM);
    cudaFuncSetAttribute(dec_kernel,   cudaFuncAttributeMaxDynamicSharedMemorySize, DEC_SMEM);

    enc1_kernel <<<NR / 64, 256, ENC_SMEM>>>(X, We1, be1);
    ppqkv_kernel<<<(NP + 63) / 64, 256, PP_SMEM>>>(We2, be2, Wq, Wk, Wv);
    attn_kernel <<<NP / 8, 256>>>(Wagg, bagg);
    dec_kernel  <<<NR / 64, 256, DEC_SMEM>>>(Wd, bd, out);
}

// round 17
// speedup vs baseline: 1.6162x; 1.1425x over previous
#include <cuda_runtime.h>
#include <cuda_bf16.h>
#include <cstdint>

typedef unsigned long long ull;

// ---------------- constants ----------------
#define BB     16
#define LL     4096
#define DD     512
#define H1     256
#define DE     64
#define STRIDE 8
#define HP     511            // patches per batch
#define NP     (BB*HP)        // 8176 patch rows
#define NR     (BB*LL)        // 65536 token rows
#define NG     (NR/8)         // 8192 groups of 8 tokens
#define EPSF   1e-8f

// ---------------- scratch (device globals; no allocation) ----------------
__device__ float g_G [(size_t)NG * H1];   // 8-token group sums of H (8 MB)
__device__ float g_qn[(size_t)NP * DE];
__device__ float g_kn[(size_t)NP * DE];
__device__ float g_v [(size_t)NP * DE];
__device__ float g_z [(size_t)NP * DE];
__device__ __nv_bfloat16 g_W1h[(size_t)H1 * DD];  // W1^T hi  [256 n][512 k]
__device__ __nv_bfloat16 g_W1l[(size_t)H1 * DD];  // W1^T lo

// ---------------- helpers ----------------
__device__ __forceinline__ ull ffma2(ull a, ull b, ull c) {
    ull d;
    asm("fma.rn.f32x2 %0, %1, %2, %3;" : "=l"(d) : "l"(a), "l"(b), "l"(c));
    return d;
}
__device__ __forceinline__ ull pack2(float lo, float hi) {
    ull r;
    asm("mov.b64 %0, {%1, %2};" : "=l"(r) : "f"(lo), "f"(hi));
    return r;
}
__device__ __forceinline__ float leaky(float x) { return x > 0.f ? x : 0.01f * x; }

// bf16 hi/lo split of a float pair into packed b32 words
__device__ __forceinline__ void split2(float x, float y, uint32_t& H, uint32_t& L) {
    __nv_bfloat162 h = __floats2bfloat162_rn(x, y);
    float rx = x - __bfloat162float(h.x);
    float ry = y - __bfloat162float(h.y);
    __nv_bfloat162 l = __floats2bfloat162_rn(rx, ry);
    H = *reinterpret_cast<uint32_t*>(&h);
    L = *reinterpret_cast<uint32_t*>(&l);
}

// m16n8k16 bf16 mma, fp32 accum
#define MMA_BF16(d, a, b0, b1) \
    asm volatile("mma.sync.aligned.m16n8k16.row.col.f32.bf16.bf16.f32 " \
        "{%0,%1,%2,%3}, {%4,%5,%6,%7}, {%8,%9}, {%0,%1,%2,%3};" \
        : "+f"((d)[0]), "+f"((d)[1]), "+f"((d)[2]), "+f"((d)[3]) \
        : "r"((a)[0]), "r"((a)[1]), "r"((a)[2]), "r"((a)[3]), "r"(b0), "r"(b1))

// ============================================================
// Kernel 0: split + transpose W1 -> g_W1h/g_W1l  ([256 n][512 k] bf16)
// ============================================================
__global__ void __launch_bounds__(256)
w1split_kernel(const float* __restrict__ We1)
{
    int idx = blockIdx.x * 256 + threadIdx.x;   // 131072 total
    int n = idx >> 9, k = idx & 511;
    float v = We1[(size_t)k * H1 + n];
    __nv_bfloat16 hb = __float2bfloat16(v);
    __nv_bfloat16 lb = __float2bfloat16(v - __bfloat162float(hb));
    g_W1h[idx] = hb;
    g_W1l[idx] = lb;
}

// ============================================================
// Kernel 1: encoder stage1 via mma.sync bf16 hi/lo split (3 passes).
// Block: 128(M) x 128(N), K=512 in 8 tiles of 64.  8 warps = 4M x 2N,
// warp tile 32x64.  Smem: k-pair words, row stride 33 (conflict-free).
// Epilogue: bias + leaky + 8-row group sums -> g_G.
// ============================================================
#define AH_OFF 0
#define AL_OFF 4224
#define BH_OFF 8448
#define BL_OFF 12672
#define ENC1_SMEM (16896 * 4)   // 67584 B

__global__ void __launch_bounds__(256, 2)
enc1_kernel(const float* __restrict__ X, const float* __restrict__ be1)
{
    extern __shared__ uint32_t sw[];
    uint32_t* Ah = sw + AH_OFF;
    uint32_t* Al = sw + AL_OFF;
    uint32_t* Bh = sw + BH_OFF;
    uint32_t* Bl = sw + BL_OFF;

    const int tid  = threadIdx.x;
    const int w    = tid >> 5;
    const int lane = tid & 31;
    const int mw   = w & 3;          // 0..3 : M block of 32
    const int nw   = w >> 2;         // 0..1 : N block of 64
    const int lr   = lane >> 2;      // 0..7
    const int lc   = lane & 3;       // 0..3
    const int r0   = blockIdx.x * 128;
    const int nc0  = blockIdx.y * 128;

    float acc[2][8][4];
    #pragma unroll
    for (int mi = 0; mi < 2; ++mi)
        #pragma unroll
        for (int ni = 0; ni < 8; ++ni)
            #pragma unroll
            for (int j = 0; j < 4; ++j) acc[mi][ni][j] = 0.f;

    const int arow = tid >> 1, ah = tid & 1;   // A: row (0..127), half (32 floats)
    const int bn = tid >> 1, bhf = tid & 1;    // B: n-row (0..127), half (16 words)

    for (int tile = 0; tile < 8; ++tile) {
        const int kt = tile * 64;
        // ---- stage A [128][64] hi/lo : 32 floats -> 16 k-pair words per thread ----
        {
            const float4* ap = (const float4*)(X + (size_t)(r0 + arow) * DD + kt + ah * 32);
            uint32_t* dh = Ah + arow * 33 + ah * 16;
            uint32_t* dl = Al + arow * 33 + ah * 16;
            #pragma unroll
            for (int j = 0; j < 8; ++j) {
                float4 f = ap[j];
                uint32_t h0, l0, h1, l1;
                split2(f.x, f.y, h0, l0);
                split2(f.z, f.w, h1, l1);
                dh[j * 2] = h0; dh[j * 2 + 1] = h1;
                dl[j * 2] = l0; dl[j * 2 + 1] = l1;
            }
        }
        // ---- stage B [128][64] hi/lo from prepacked W1^T ----
        {
            const uint4* gh = (const uint4*)(g_W1h + (size_t)(nc0 + bn) * DD + kt + bhf * 32);
            const uint4* gl = (const uint4*)(g_W1l + (size_t)(nc0 + bn) * DD + kt + bhf * 32);
            uint32_t* dhw = Bh + bn * 33 + bhf * 16;
            uint32_t* dlw = Bl + bn * 33 + bhf * 16;
            #pragma unroll
            for (int j = 0; j < 4; ++j) {
                uint4 vh = gh[j], vl = gl[j];
                dhw[j*4+0]=vh.x; dhw[j*4+1]=vh.y; dhw[j*4+2]=vh.z; dhw[j*4+3]=vh.w;
                dlw[j*4+0]=vl.x; dlw[j*4+1]=vl.y; dlw[j*4+2]=vl.z; dlw[j*4+3]=vl.w;
            }
        }
        __syncthreads();

        #pragma unroll
        for (int ks = 0; ks < 4; ++ks) {
            const int kb = ks * 8 + lc;
            uint32_t a_h[2][4], a_l[2][4];
            #pragma unroll
            for (int mi = 0; mi < 2; ++mi) {
                int rbase = (mw * 32 + mi * 16 + lr) * 33 + kb;
                a_h[mi][0] = Ah[rbase];            a_h[mi][1] = Ah[rbase + 8 * 33];
                a_h[mi][2] = Ah[rbase + 4];        a_h[mi][3] = Ah[rbase + 8 * 33 + 4];
                a_l[mi][0] = Al[rbase];            a_l[mi][1] = Al[rbase + 8 * 33];
                a_l[mi][2] = Al[rbase + 4];        a_l[mi][3] = Al[rbase + 8 * 33 + 4];
            }
            #pragma unroll
            for (int ni = 0; ni < 8; ++ni) {
                int nbase = (nw * 64 + ni * 8 + lr) * 33 + kb;
                uint32_t bh0 = Bh[nbase], bh1 = Bh[nbase + 4];
                uint32_t bl0 = Bl[nbase], bl1 = Bl[nbase + 4];
                #pragma unroll
                for (int mi = 0; mi < 2; ++mi) {
                    MMA_BF16(acc[mi][ni], a_h[mi], bh0, bh1);
                    MMA_BF16(acc[mi][ni], a_h[mi], bl0, bl1);
                    MMA_BF16(acc[mi][ni], a_l[mi], bh0, bh1);
                }
            }
        }
        __syncthreads();
    }

    // ---- epilogue: bias + leaky + 8-row group sums -> g_G ----
    // D frag: c0,c1 at row lr, cols lc*2, lc*2+1; c2,c3 at row lr+8.
    const int gbase = blockIdx.x * 16 + mw * 4;
    #pragma unroll
    for (int mi = 0; mi < 2; ++mi) {
        #pragma unroll
        for (int ni = 0; ni < 8; ++ni) {
            int col = nc0 + nw * 64 + ni * 8 + lc * 2;
            float2 bb = *(const float2*)(be1 + col);
            float v0 = leaky(acc[mi][ni][0] + bb.x);
            float v1 = leaky(acc[mi][ni][1] + bb.y);
            float v2 = leaky(acc[mi][ni][2] + bb.x);
            float v3 = leaky(acc[mi][ni][3] + bb.y);
            #pragma unroll
            for (int off = 16; off >= 4; off >>= 1) {
                v0 += __shfl_xor_sync(0xffffffffu, v0, off);
                v1 += __shfl_xor_sync(0xffffffffu, v1, off);
                v2 += __shfl_xor_sync(0xffffffffu, v2, off);
                v3 += __shfl_xor_sync(0xffffffffu, v3, off);
            }
            if (lane < 4) {
                *(float2*)(g_G + (size_t)(gbase + mi * 2)     * H1 + col) = make_float2(v0, v1);
                *(float2*)(g_G + (size_t)(gbase + mi * 2 + 1) * H1 + col) = make_float2(v2, v3);
            }
        }
    }
}

// ============================================================
// Kernel 2: per-patch pp = ((G[p]+G[p+1])/16) @ W2 + b2, then
// q,k,v = pp @ Wq/Wk/Wv, normalize q,k.  64 patches/block, 256 thr.
// ============================================================
#define SROW 260
#define PROW 68
#define PP_SMEM (64*SROW*4 + 256*64*4 + 64*PROW*4)

__global__ void __launch_bounds__(256)
ppqkv_kernel(const float* __restrict__ W2, const float* __restrict__ b2,
             const float* __restrict__ Wq, const float* __restrict__ Wk,
             const float* __restrict__ Wv)
{
    extern __shared__ unsigned char sm[];
    float* S   = (float*)sm;                       // [64][260]
    float* W2s = (float*)(sm + 64*SROW*4);         // [256][64]
    float* PPs = (float*)(sm + 64*SROW*4 + 65536); // [64][68]
    float* Wqs = (float*)sm;
    float* Wks = (float*)(sm + 16384);
    float* Wvs = (float*)(sm + 32768);

    const int tid = threadIdx.x;
    const int blk = blockIdx.x;

    for (int idx = tid; idx < 64 * 64; idx += 256) {
        int i = idx >> 6, e4 = (idx & 63) * 4;
        int n = blk * 64 + i;
        float4 v = make_float4(0.f, 0.f, 0.f, 0.f);
        if (n < NP) {
            int b = n / HP, p = n - b * HP;
            const float* g0 = g_G + ((size_t)b * 512 + p) * H1 + e4;
            float4 a = *(const float4*)g0;
            float4 c = *(const float4*)(g0 + H1);
            v = make_float4((a.x + c.x) * 0.0625f, (a.y + c.y) * 0.0625f,
                            (a.z + c.z) * 0.0625f, (a.w + c.w) * 0.0625f);
        }
        *(float4*)&S[i * SROW + e4] = v;
    }
    for (int idx = tid; idx < 4096; idx += 256)
        ((float4*)W2s)[idx] = ((const float4*)W2)[idx];
    __syncthreads();

    const int i  = tid >> 2;
    const int d0 = (tid & 3) * 16;

    float accA[16];
    {
        const float4* bp = (const float4*)(b2 + d0);
        #pragma unroll
        for (int j = 0; j < 4; ++j) {
            float4 b4 = bp[j];
            accA[j*4+0]=b4.x; accA[j*4+1]=b4.y; accA[j*4+2]=b4.z; accA[j*4+3]=b4.w;
        }
    }
    for (int e = 0; e < H1; ++e) {
        float s = S[i * SROW + e];
        const float4* wr = (const float4*)(W2s + e * 64 + d0);
        #pragma unroll
        for (int j = 0; j < 4; ++j) {
            float4 w4 = wr[j];
            accA[j*4+0] = fmaf(s, w4.x, accA[j*4+0]);
            accA[j*4+1] = fmaf(s, w4.y, accA[j*4+1]);
            accA[j*4+2] = fmaf(s, w4.z, accA[j*4+2]);
            accA[j*4+3] = fmaf(s, w4.w, accA[j*4+3]);
        }
    }
    #pragma unroll
    for (int j = 0; j < 4; ++j)
        *(float4*)&PPs[i * PROW + d0 + j * 4] =
            make_float4(accA[j*4+0], accA[j*4+1], accA[j*4+2], accA[j*4+3]);
    __syncthreads();

    for (int idx = tid; idx < 1024; idx += 256) {
        ((float4*)Wqs)[idx] = ((const float4*)Wq)[idx];
        ((float4*)Wks)[idx] = ((const float4*)Wk)[idx];
        ((float4*)Wvs)[idx] = ((const float4*)Wv)[idx];
    }
    __syncthreads();

    float q[16], kk[16], vv[16];
    #pragma unroll
    for (int j = 0; j < 16; ++j) { q[j] = 0.f; kk[j] = 0.f; vv[j] = 0.f; }
    for (int e = 0; e < 64; ++e) {
        float p = PPs[i * PROW + e];
        const float4* wq = (const float4*)(Wqs + e * 64 + d0);
        const float4* wk = (const float4*)(Wks + e * 64 + d0);
        const float4* wv = (const float4*)(Wvs + e * 64 + d0);
        #pragma unroll
        for (int j = 0; j < 4; ++j) {
            float4 a = wq[j], b = wk[j], c = wv[j];
            q [j*4+0]=fmaf(p,a.x,q [j*4+0]); q [j*4+1]=fmaf(p,a.y,q [j*4+1]);
            q [j*4+2]=fmaf(p,a.z,q [j*4+2]); q [j*4+3]=fmaf(p,a.w,q [j*4+3]);
            kk[j*4+0]=fmaf(p,b.x,kk[j*4+0]); kk[j*4+1]=fmaf(p,b.y,kk[j*4+1]);
            kk[j*4+2]=fmaf(p,b.z,kk[j*4+2]); kk[j*4+3]=fmaf(p,b.w,kk[j*4+3]);
            vv[j*4+0]=fmaf(p,c.x,vv[j*4+0]); vv[j*4+1]=fmaf(p,c.y,vv[j*4+1]);
            vv[j*4+2]=fmaf(p,c.z,vv[j*4+2]); vv[j*4+3]=fmaf(p,c.w,vv[j*4+3]);
        }
    }
    float q2 = 0.f, k2 = 0.f;
    #pragma unroll
    for (int j = 0; j < 16; ++j) { q2 = fmaf(q[j], q[j], q2); k2 = fmaf(kk[j], kk[j], k2); }
    q2 += __shfl_xor_sync(0xffffffffu, q2, 1); q2 += __shfl_xor_sync(0xffffffffu, q2, 2);
    k2 += __shfl_xor_sync(0xffffffffu, k2, 1); k2 += __shfl_xor_sync(0xffffffffu, k2, 2);
    float invq = 1.0f / (sqrtf(q2) + EPSF);
    float invk = 1.0f / (sqrtf(k2) + EPSF);

    int n = blk * 64 + i;
    if (n < NP) {
        float* dq = g_qn + (size_t)n * 64 + d0;
        float* dk = g_kn + (size_t)n * 64 + d0;
        float* dv = g_v  + (size_t)n * 64 + d0;
        #pragma unroll
        for (int j = 0; j < 4; ++j) {
            *(float4*)(dq + j*4) = make_float4(q [j*4]*invq, q [j*4+1]*invq, q [j*4+2]*invq, q [j*4+3]*invq);
            *(float4*)(dk + j*4) = make_float4(kk[j*4]*invk, kk[j*4+1]*invk, kk[j*4+2]*invk, kk[j*4+3]*invk);
            *(float4*)(dv + j*4) = make_float4(vv[j*4],      vv[j*4+1],      vv[j*4+2],      vv[j*4+3]);
        }
    }
}

// ============================================================
// Kernel 3: attention. Warp per patch, 8 patches/block.
// ============================================================
__global__ void __launch_bounds__(256)
attn_kernel(const float* __restrict__ Wagg, const float* __restrict__ bagg)
{
    __shared__ float sq[8][64], sk[8][64], sav[8][64];
    __shared__ float Wgs[64 * 64];

    const int tid = threadIdx.x;
    const int w = tid >> 5, lane = tid & 31;
    const int n = blockIdx.x * 8 + w;

    for (int idx = tid; idx < 1024; idx += 256)
        ((float4*)Wgs)[idx] = ((const float4*)Wagg)[idx];

    const size_t base = (size_t)n * 64;
    float q0 = g_qn[base + lane], q1 = g_qn[base + lane + 32];
    float k0 = g_kn[base + lane], k1 = g_kn[base + lane + 32];
    float v0 = g_v [base + lane], v1 = g_v [base + lane + 32];
    sq[w][lane] = q0; sq[w][lane + 32] = q1;
    sk[w][lane] = k0; sk[w][lane + 32] = k1;
    __syncthreads();

    for (int i = 0; i < 64; ++i) {
        float qi = sq[w][i], ki = sk[w][i];
        float a0 = fmaxf(tanhf(qi * k0 - ki * q0), 0.f);
        float a1 = fmaxf(tanhf(qi * k1 - ki * q1), 0.f);
        unsigned key0 = (__float_as_uint(a0) & 0xFFFFFFC0u) | (63u - (unsigned)lane);
        unsigned key1 = (__float_as_uint(a1) & 0xFFFFFFC0u) | (31u - (unsigned)lane);
        unsigned keep0 = 0u, keep1 = 0u;
        #pragma unroll
        for (int it = 0; it < 8; ++it) {
            unsigned mk = key0 > key1 ? key0 : key1;
            unsigned win = __reduce_max_sync(0xffffffffu, mk);
            if (key0 == win)      { keep0 = 1u; key0 = 0u; }
            else if (key1 == win) { keep1 = 1u; key1 = 0u; }
        }
        float fa0 = keep0 ? a0 : 0.f;
        float fa1 = keep1 ? a1 : 0.f;
        float contrib = fa0 * v0 + fa1 * v1;
        float suma    = fa0 + fa1;
        #pragma unroll
        for (int off = 16; off; off >>= 1) {
            contrib += __shfl_xor_sync(0xffffffffu, contrib, off);
            suma    += __shfl_xor_sync(0xffffffffu, suma, off);
        }
        if (lane == 0) sav[w][i] = contrib / fmaxf(suma, EPSF);
    }
    __syncwarp();

    float acc0 = bagg[lane], acc1 = bagg[lane + 32];
    #pragma unroll 8
    for (int e = 0; e < 64; ++e) {
        float ae = sav[w][e];
        acc0 = fmaf(ae, Wgs[e * 64 + lane],      acc0);
        acc1 = fmaf(ae, Wgs[e * 64 + lane + 32], acc1);
    }
    g_z[base + lane]      = leaky(acc0);
    g_z[base + lane + 32] = leaky(acc1);
}

// ============================================================
// Kernel 4: overlap-average gather + decoder GEMM (64 rows/block)
// ============================================================
#define DEC_SMEM (131072 + 64*66*8)

__global__ void __launch_bounds__(256, 1)
dec_kernel(const float* __restrict__ Wd, const float* __restrict__ bd,
           float* __restrict__ out)
{
    extern __shared__ unsigned char sm[];
    float* Ws = (float*)sm;                                   // [64][512]
    ull (*us2)[66] = reinterpret_cast<ull(*)[66]>(sm + 131072);

    const int tid = threadIdx.x;
    const int row0 = blockIdx.x * 64;

    {
        const float4* src = (const float4*)Wd;
        float4* dst = (float4*)Ws;
        #pragma unroll
        for (int i = 0; i < 32; ++i) dst[tid + i * 256] = src[tid + i * 256];
    }
    {
        int d = tid & 63;
        #pragma unroll
        for (int i = 0; i < 16; ++i) {
            int rloc = (tid >> 6) + 4 * i;
            int rg = row0 + rloc;
            int bb = rg >> 12;
            int l  = rg & 4095;
            int phi = l >> 3;        if (phi > HP - 1) phi = HP - 1;
            int plo = (l - 8) >> 3;  if (plo < 0) plo = 0;
            float s = g_z[((size_t)bb * HP + plo) * 64 + d];
            float scale = 1.0f;
            if (phi > plo) { s += g_z[((size_t)bb * HP + phi) * 64 + d]; scale = 0.5f; }
            float u = s * scale;
            us2[rloc][d] = pack2(u, u);
        }
    }
    __syncthreads();

    const int w = tid >> 5, lane = tid & 31;
    const int rb = w * 8;
    const int c4 = lane * 4;

    #pragma unroll
    for (int ch = 0; ch < 2; ++ch) {
        const int cb = ch * 256;
        ull acc[8][4];
        {
            float4 blo = *(const float4*)(bd + cb + c4);
            float4 bhi = *(const float4*)(bd + cb + 128 + c4);
            ull a0 = pack2(blo.x, blo.y), a1 = pack2(blo.z, blo.w);
            ull a2 = pack2(bhi.x, bhi.y), a3 = pack2(bhi.z, bhi.w);
            #pragma unroll
            for (int r = 0; r < 8; ++r) { acc[r][0]=a0; acc[r][1]=a1; acc[r][2]=a2; acc[r][3]=a3; }
        }
        #pragma unroll 8
        for (int k = 0; k < 64; k += 2) {
            ulonglong2 bA0 = *(const ulonglong2*)&Ws[k * 512 + cb + c4];
            ulonglong2 bA1 = *(const ulonglong2*)&Ws[k * 512 + cb + 128 + c4];
            ulonglong2 bB0 = *(const ulonglong2*)&Ws[(k + 1) * 512 + cb + c4];
            ulonglong2 bB1 = *(const ulonglong2*)&Ws[(k + 1) * 512 + cb + 128 + c4];
            #pragma unroll
            for (int r = 0; r < 8; ++r) {
                ulonglong2 a = *(const ulonglong2*)&us2[rb + r][k];
                acc[r][0] = ffma2(a.x, bA0.x, acc[r][0]);
                acc[r][1] = ffma2(a.x, bA0.y, acc[r][1]);
                acc[r][2] = ffma2(a.x, bA1.x, acc[r][2]);
                acc[r][3] = ffma2(a.x, bA1.y, acc[r][3]);
                acc[r][0] = ffma2(a.y, bB0.x, acc[r][0]);
                acc[r][1] = ffma2(a.y, bB0.y, acc[r][1]);
                acc[r][2] = ffma2(a.y, bB1.x, acc[r][2]);
                acc[r][3] = ffma2(a.y, bB1.y, acc[r][3]);
            }
        }
        #pragma unroll
        for (int r = 0; r < 8; ++r) {
            float* op = out + (size_t)(row0 + rb + r) * 512 + cb;
            ulonglong2 s0; s0.x = acc[r][0]; s0.y = acc[r][1];
            ulonglong2 s1; s1.x = acc[r][2]; s1.y = acc[r][3];
            *(ulonglong2*)(op + c4)       = s0;
            *(ulonglong2*)(op + 128 + c4) = s1;
        }
    }
}

// ============================================================
extern "C" void kernel_launch(void* const* d_in, const int* in_sizes, int n_in,
                              void* d_out, int out_size)
{
    const float* X    = (const float*)d_in[0];
    const float* We1  = (const float*)d_in[1];
    const float* be1  = (const float*)d_in[2];
    const float* We2  = (const float*)d_in[3];
    const float* be2  = (const float*)d_in[4];
    const float* Wq   = (const float*)d_in[5];
    const float* Wk   = (const float*)d_in[6];
    const float* Wv   = (const float*)d_in[7];
    const float* Wagg = (const float*)d_in[8];
    const float* bagg = (const float*)d_in[9];
    const float* Wd   = (const float*)d_in[10];
    const float* bd   = (const float*)d_in[11];
    float* out = (float*)d_out;

    cudaFuncSetAttribute(enc1_kernel,  cudaFuncAttributeMaxDynamicSharedMemorySize, ENC1_SMEM);
    cudaFuncSetAttribute(ppqkv_kernel, cudaFuncAttributeMaxDynamicSharedMemorySize, PP_SMEM);
    cudaFuncSetAttribute(dec_kernel,   cudaFuncAttributeMaxDynamicSharedMemorySize, DEC_SMEM);

    w1split_kernel<<<512, 256>>>(We1);
    {
        dim3 grid(NR / 128, 2);
        enc1_kernel<<<grid, 256, ENC1_SMEM>>>(X, be1);
    }
    ppqkv_kernel<<<(NP + 63) / 64, 256, PP_SMEM>>>(We2, be2, Wq, Wk, Wv);
    attn_kernel <<<NP / 8, 256>>>(Wagg, bagg);
    dec_kernel  <<<NR / 64, 256, DEC_SMEM>>>(Wd, bd, out);
}